// round 17
// baseline (speedup 1.0000x reference)
#include <cuda_runtime.h>

#define B 64
#define H 768
#define E 128

#define NRED 256    // core-reduce blocks (32 KB each), bids [0,256)
#define KS 12       // GEMM k-splits
#define NGEMM 192   // 12 ks x 8 echunk x 2 bgroup, bids [256,448)
#define GRID (NRED + NGEMM)
#define NGRP 16     // GEMM groups (one per (ec,bg) tile)

__device__ float g_S2p[NRED];          // core partials (2 per leading index i)
__device__ float g_P[3][KS][B][E];     // [mat][ks][b][e] gemm partials
__device__ float g_Pf[3][B][E];        // ks-folded partials (written by folders)
__device__ unsigned g_gc[NGRP];        // per-group fold counters; self-reset
__device__ unsigned g_arrive;          // global arrive counter; self-reset

__global__ void __launch_bounds__(256)
k_all(const float* __restrict__ core,
      const float* __restrict__ hs, const float* __restrict__ rs,
      const float* __restrict__ ts, const float* __restrict__ we,
      const float* __restrict__ wr, const float* __restrict__ be,
      const float* __restrict__ br, float* __restrict__ out) {
    __shared__ float4 s_src[3][32][18];  // gemm src tiles / winner scratch
    __shared__ float4 s_w[2][16][18];    // gemm W tiles / reduce scratch
    __shared__ unsigned s_tk;

    const int bid = blockIdx.x;
    const int tid = threadIdx.x;

    if (bid < NRED) {
        // ------- core reduction (R2-proven): 32 KB chunk, MLP=8 -------------
        const float4* src = reinterpret_cast<const float4*>(core) + (size_t)bid * 2048;
        const float4 v0 = __ldg(src + tid);
        const float4 v1 = __ldg(src + tid + 256);
        const float4 v2 = __ldg(src + tid + 512);
        const float4 v3 = __ldg(src + tid + 768);
        const float4 v4 = __ldg(src + tid + 1024);
        const float4 v5 = __ldg(src + tid + 1280);
        const float4 v6 = __ldg(src + tid + 1536);
        const float4 v7 = __ldg(src + tid + 1792);
        float s = ((((v0.x + v0.y) + (v0.z + v0.w)) + ((v1.x + v1.y) + (v1.z + v1.w)))
                +  (((v2.x + v2.y) + (v2.z + v2.w)) + ((v3.x + v3.y) + (v3.z + v3.w))))
                + ((((v4.x + v4.y) + (v4.z + v4.w)) + ((v5.x + v5.y) + (v5.z + v5.w)))
                +  (((v6.x + v6.y) + (v6.z + v6.w)) + ((v7.x + v7.y) + (v7.z + v7.w))));
#pragma unroll
        for (int o = 16; o > 0; o >>= 1) s += __shfl_xor_sync(0xffffffffu, s, o);
        float* ws = reinterpret_cast<float*>(s_w);
        if ((tid & 31) == 0) ws[tid >> 5] = s;
        __syncthreads();
        if (tid == 0) {
            float tot = 0.f;
#pragma unroll
            for (int w = 0; w < 8; w++) tot += ws[w];
            g_S2p[bid] = tot;
        }
    } else {
        // ------- triple GEMM (R2-proven, plain stores): 32b x 16e x 64k -----
        const int lin = bid - NRED;
        const int ks = lin % KS;
        const int gid = lin / KS;            // 0..15
        const int ec = gid & 7, bg = gid >> 3;
        const int b0 = bg * 32, e0 = ec * 16;
        const int c0 = ks * 16;

        const float4* g0 = reinterpret_cast<const float4*>(hs);
        const float4* g1 = reinterpret_cast<const float4*>(rs);
        const float4* g2 = reinterpret_cast<const float4*>(ts);
#pragma unroll
        for (int i = tid; i < 512; i += 256) {
            const int row = i >> 4, c4 = i & 15;
            const size_t gidx = (size_t)(b0 + row) * 192 + c0 + c4;
            const int sc = c4 ^ (row & 7);
            s_src[0][row][sc] = g0[gidx];
            s_src[1][row][sc] = g1[gidx];
            s_src[2][row][sc] = g2[gidx];
        }
        {
            const int row = tid >> 4, c4 = tid & 15;
            const size_t gidx = (size_t)(e0 + row) * 192 + c0 + c4;
            const int sc = c4 ^ (row & 7);
            s_w[0][row][sc] = reinterpret_cast<const float4*>(we)[gidx];
            s_w[1][row][sc] = reinterpret_cast<const float4*>(wr)[gidx];
        }
        __syncthreads();

        const int te = tid & 15;
        const int tb = tid >> 4;
        const int ba = 2 * tb, bb = ba + 1;

        float h0 = 0.f, h1 = 0.f, r0 = 0.f, r1 = 0.f, t0 = 0.f, t1 = 0.f;
#pragma unroll
        for (int k4 = 0; k4 < 16; k4++) {
            const float4 vwe = s_w[0][te][k4 ^ (te & 7)];
            const float4 vwr = s_w[1][te][k4 ^ (te & 7)];
            const int sa = k4 ^ (ba & 7), sb = k4 ^ (bb & 7);
            float4 a, c;
            a = s_src[0][ba][sa]; c = s_src[0][bb][sb];
            h0 += vwe.x * a.x + vwe.y * a.y + vwe.z * a.z + vwe.w * a.w;
            h1 += vwe.x * c.x + vwe.y * c.y + vwe.z * c.z + vwe.w * c.w;
            a = s_src[1][ba][sa]; c = s_src[1][bb][sb];
            r0 += vwr.x * a.x + vwr.y * a.y + vwr.z * a.z + vwr.w * a.w;
            r1 += vwr.x * c.x + vwr.y * c.y + vwr.z * c.z + vwr.w * c.w;
            a = s_src[2][ba][sa]; c = s_src[2][bb][sb];
            t0 += vwe.x * a.x + vwe.y * a.y + vwe.z * a.z + vwe.w * a.w;
            t1 += vwe.x * c.x + vwe.y * c.y + vwe.z * c.z + vwe.w * c.w;
        }

        const int bga = b0 + ba, bgb = b0 + bb;
        const int e = e0 + te;
        g_P[0][ks][bga][e] = h0;  g_P[0][ks][bgb][e] = h1;
        g_P[1][ks][bga][e] = r0;  g_P[1][ks][bgb][e] = r1;
        g_P[2][ks][bga][e] = t0;  g_P[2][ks][bgb][e] = t1;

        // ---- last block of this group folds its 12 ks slices ---------------
        __threadfence();
        __syncthreads();
        if (tid == 0) s_tk = atomicAdd(&g_gc[gid], 1u);
        __syncthreads();
        if (s_tk == KS - 1) {                 // uniform across block
            __threadfence();
            // 384 float4 outputs: [m:3][bl:32][e4:4]; thread does <=2
            for (int item = tid; item < 384; item += 256) {
                const int m = item >> 7, rem = item & 127;
                const int bl = rem >> 2, e4l = rem & 3;
                const float4* p = reinterpret_cast<const float4*>(
                                      &g_P[m][0][b0 + bl][e0]) + e4l;
                float4 acc = make_float4(0.f, 0.f, 0.f, 0.f);
#pragma unroll
                for (int k = 0; k < KS; k++) {
                    const float4 v = __ldg(p + k * 2048);  // ks stride = B*E/4
                    acc.x += v.x; acc.y += v.y; acc.z += v.z; acc.w += v.w;
                }
                *(reinterpret_cast<float4*>(&g_Pf[m][b0 + bl][e0]) + e4l) = acc;
            }
            __threadfence();
            __syncthreads();
            if (tid == 0) g_gc[gid] = 0;      // reset for next replay
        }
    }

    // ---------------- global arrive; LAST block does the combine -----------
    __syncthreads();
    if (tid == 0) {
        __threadfence();
        s_tk = atomicAdd(&g_arrive, 1u);
    }
    __syncthreads();
    if (s_tk != GRID - 1) return;             // no one waits

    // ---------------- winner combine (the straggler itself) ----------------
    __threadfence();
    float* s_s2 = reinterpret_cast<float*>(s_src);   // 128
    float* s_be = s_s2 + 128;                        // 128
    float* s_br = s_s2 + 256;                        // 128
    if (tid < 128) {
        s_s2[tid] = g_S2p[2 * tid] + g_S2p[2 * tid + 1];
        s_be[tid] = be[tid];
        s_br[tid] = br[tid];
    }
    __syncthreads();

    const int b = tid >> 2, q = tid & 3;      // 64 b x 4 quads
    const float4* ph = reinterpret_cast<const float4*>(&g_Pf[0][b][0]);
    const float4* pr = reinterpret_cast<const float4*>(&g_Pf[1][b][0]);
    const float4* pt = reinterpret_cast<const float4*>(&g_Pf[2][b][0]);
    float acc = 0.f;
#pragma unroll 4
    for (int j = 0; j < 8; j++) {
        const int e4 = j * 4 + q;             // interleaved -> coalesced quads
        const float4 h4 = __ldg(ph + e4);
        const float4 r4 = __ldg(pr + e4);
        const float4 t4 = __ldg(pt + e4);
        const int e = e4 * 4;
        acc += (h4.x + s_be[e])     * (r4.x + s_br[e])     * (t4.x + s_be[e])     * s_s2[e];
        acc += (h4.y + s_be[e + 1]) * (r4.y + s_br[e + 1]) * (t4.y + s_be[e + 1]) * s_s2[e + 1];
        acc += (h4.z + s_be[e + 2]) * (r4.z + s_br[e + 2]) * (t4.z + s_be[e + 2]) * s_s2[e + 2];
        acc += (h4.w + s_be[e + 3]) * (r4.w + s_br[e + 3]) * (t4.w + s_be[e + 3]) * s_s2[e + 3];
    }
    acc += __shfl_xor_sync(0xffffffffu, acc, 1);
    acc += __shfl_xor_sync(0xffffffffu, acc, 2);
    if (q == 0) out[b] = -acc;

    __syncthreads();
    if (tid == 0) {                            // reset for next graph replay
        g_arrive = 0u;
        __threadfence();
    }
}

// ---------------------------------------------------------------------------
extern "C" void kernel_launch(void* const* d_in, const int* in_sizes, int n_in,
                              void* d_out, int out_size) {
    const float* head = (const float*)d_in[0];
    const float* rel  = (const float*)d_in[1];
    const float* tail = (const float*)d_in[2];
    const float* We   = (const float*)d_in[3];
    const float* be   = (const float*)d_in[4];
    const float* Wr   = (const float*)d_in[5];
    const float* br   = (const float*)d_in[6];
    const float* core = (const float*)d_in[7];
    float* out = (float*)d_out;

    k_all<<<GRID, 256>>>(core, head, rel, tail, We, Wr, be, br, out);
}